// round 1
// baseline (speedup 1.0000x reference)
#include <cuda_runtime.h>
#include <math.h>

#define NL 4
#define NB 32
#define NH 512
#define NV 32000
#define NT 51

typedef unsigned long long u64;

// -------- persistent device scratch (zero-initialized at module load) --------
__device__ float g_h[2][NL][NB][NH];     // ping-pong hidden state (clamped)
__device__ float g_c[NL][NB][NH];        // cell state (clamped), elementwise per block -> no ping-pong
__device__ float g_xbuf[2][NB][NH];      // inter-layer activations (unclamped h)
__device__ float g_htop[1664 * NH];      // top-layer hidden per step, padded 1632 -> 1664 rows

// -------- packed f32x2 helpers (sm_103a FFMA2 path) --------
__device__ __forceinline__ u64 pk2(float lo, float hi) {
    u64 r;
    asm("mov.b64 %0, {%1, %2};" : "=l"(r) : "r"(__float_as_uint(lo)), "r"(__float_as_uint(hi)));
    return r;
}
__device__ __forceinline__ void upk2(u64 v, float &lo, float &hi) {
    unsigned a, b;
    asm("mov.b64 {%0, %1}, %2;" : "=r"(a), "=r"(b) : "l"(v));
    lo = __uint_as_float(a); hi = __uint_as_float(b);
}
__device__ __forceinline__ u64 ffma2(u64 a, u64 b, u64 c) {
    u64 d;
    asm("fma.rn.f32x2 %0, %1, %2, %3;" : "=l"(d) : "l"(a), "l"(b), "l"(c));
    return d;
}
__device__ __forceinline__ u64 fadd2(u64 a, u64 b) {
    u64 d;
    asm("add.rn.f32x2 %0, %1, %2;" : "=l"(d) : "l"(a), "l"(b));
    return d;
}
__device__ __forceinline__ float sigmoidf_(float x) { return 1.0f / (1.0f + expf(-x)); }
__device__ __forceinline__ float clip50(float x) { return fminf(fmaxf(x, -50.0f), 50.0f); }

// -------- state init (runs at graph start: deterministic across replays) --------
__global__ void init_states(const float* __restrict__ dh, const float* __restrict__ dc) {
    int idx = blockIdx.x * blockDim.x + threadIdx.x;   // 65536 total
    (&g_h[0][0][0][0])[idx] = dh[idx];
    (&g_c[0][0][0])[idx]    = dc[idx];
}

// -------- one LSTM layer-step --------
// grid: 128 blocks (4 hidden units each), 256 threads (8 warps).
// warp w: half = w>>2 (0: x@W_ih K-half, 1: h@W_hh K-half), gate = w&3, rows j0..j0+3.
// x||h staged in SMEM as batch-paired f32x2: xh2[b2][k], k in [0,1024).
__global__ __launch_bounds__(256) void lstm_step(
    int l, int t, int par,
    const float* __restrict__ emb, const int* __restrict__ target,
    const float* __restrict__ Wih, const float* __restrict__ Whh,
    const float* __restrict__ bih, const float* __restrict__ bhh)
{
    extern __shared__ u64 sm_[];
    u64* xh2 = sm_;                                  // [16][1024] u64 = 128KB
    float* gates_s = (float*)(sm_ + 16 * 1024);      // [2][4][4][32] = 4KB

    const int tid  = threadIdx.x;
    const int lane = tid & 31;
    const int wid  = tid >> 5;
    const int j0   = blockIdx.x * 4;

    const float* hsrc = &g_h[par][l][0][0];
    const float* xsrc = &g_xbuf[(l - 1) & 1][0][0];  // only valid for l>0

    // ---- stage x (k<512) and h_prev (k>=512) into SMEM as (b even, b odd) pairs ----
    #pragma unroll 4
    for (int idx = tid; idx < 16 * 1024; idx += 256) {
        int b2 = idx >> 10, k = idx & 1023;
        int b0 = b2 * 2, b1 = b0 + 1;
        float v0, v1;
        if (k < 512) {
            if (l == 0) {
                int t0 = (t == 0) ? 0 : target[b0 * NT + t - 1];
                int t1 = (t == 0) ? 0 : target[b1 * NT + t - 1];
                v0 = emb[t0 * 512 + k];
                v1 = emb[t1 * 512 + k];
            } else {
                v0 = xsrc[b0 * 512 + k];
                v1 = xsrc[b1 * 512 + k];
            }
        } else {
            v0 = hsrc[b0 * 512 + (k - 512)];
            v1 = hsrc[b1 * 512 + (k - 512)];
        }
        xh2[idx] = pk2(v0, v1);
    }
    __syncthreads();

    const int half = wid >> 2;
    const int gate = wid & 3;
    const float* Wsel = half ? Whh : Wih;
    const float* wbase[4];
    #pragma unroll
    for (int r = 0; r < 4; r++) {
        int n = gate * 512 + j0 + r;
        wbase[r] = Wsel + ((size_t)l * 2048 + n) * 512 + lane;
    }

    u64 acc[4][16];
    #pragma unroll
    for (int r = 0; r < 4; r++)
        #pragma unroll
        for (int b2 = 0; b2 < 16; b2++) acc[r][b2] = 0ULL;

    // ---- main dot-product loop over this warp's 512-wide K half, prefetching W ----
    float wc[4];
    #pragma unroll
    for (int r = 0; r < 4; r++) wc[r] = wbase[r][0];

    for (int kc = 0; kc < 16; kc++) {
        u64 aa[4];
        #pragma unroll
        for (int r = 0; r < 4; r++) aa[r] = pk2(wc[r], wc[r]);
        if (kc < 15) {
            #pragma unroll
            for (int r = 0; r < 4; r++) wc[r] = wbase[r][(kc + 1) * 32];
        }
        const u64* xrow = xh2 + (half * 512 + kc * 32 + lane);
        #pragma unroll
        for (int b2 = 0; b2 < 16; b2++) {
            u64 xv = xrow[b2 * 1024];
            #pragma unroll
            for (int r = 0; r < 4; r++) acc[r][b2] = ffma2(aa[r], xv, acc[r][b2]);
        }
    }

    // ---- cross-lane butterfly reduction (each lane held a k-slice) ----
    #pragma unroll
    for (int off = 16; off > 0; off >>= 1) {
        #pragma unroll
        for (int r = 0; r < 4; r++)
            #pragma unroll
            for (int b2 = 0; b2 < 16; b2++)
                acc[r][b2] = fadd2(acc[r][b2], __shfl_xor_sync(0xffffffffu, acc[r][b2], off));
    }

    if (lane < 16) {
        #pragma unroll
        for (int r = 0; r < 4; r++)
            *(u64*)&gates_s[(((half * 4 + gate) * 4) + r) * 32 + 2 * lane] = acc[r][lane];
    }
    __syncthreads();

    // ---- pointwise cell update: 4 j x 32 b = 128 elements ----
    if (tid < 128) {
        int jl = tid >> 5, b = tid & 31;
        int j = j0 + jl;
        float gv[4];
        #pragma unroll
        for (int g = 0; g < 4; g++) {
            int n = g * 512 + j;
            gv[g] = gates_s[((0 * 4 + g) * 4 + jl) * 32 + b]
                  + gates_s[((1 * 4 + g) * 4 + jl) * 32 + b]
                  + bih[l * 2048 + n] + bhh[l * 2048 + n];
        }
        float iv = sigmoidf_(gv[0]);
        float fv = sigmoidf_(gv[1]);
        float gg = tanhf(gv[2]);
        float ov = sigmoidf_(gv[3]);
        float cold = g_c[l][b][j];
        float cnew = fv * cold + iv * gg;
        float hnew = ov * tanhf(cnew);
        g_xbuf[l & 1][b][j] = hnew;                            // unclamped -> next layer
        if (l == 3) g_htop[((size_t)t * 32 + b) * 512 + j] = hnew;  // unclamped -> projection
        g_c[l][b][j] = clip50(cnew);                           // clamped carry
        g_h[par ^ 1][l][b][j] = clip50(hnew);                  // clamped carry (ping-pong)
    }
}

// -------- batched output projection: C[1664,32000] = htop @ Wout^T + bout --------
// BM=64, BN=128, 256 threads, per-thread 4m x 8n as 4x4 f32x2 accumulators.
__global__ __launch_bounds__(256) void proj_gemm(
    const float* __restrict__ Wout, const float* __restrict__ bout,
    float* __restrict__ out)
{
    __shared__ float As[32][64];     // [k][m]
    __shared__ float Bs[32][128];    // [k][n]
    const int tid = threadIdx.x;
    const int tx = tid & 15;
    const int ty = tid >> 4;
    const int bm = blockIdx.y * 64;
    const int bn = blockIdx.x * 128;

    u64 acc[4][4];
    #pragma unroll
    for (int i = 0; i < 4; i++)
        #pragma unroll
        for (int j = 0; j < 4; j++) acc[i][j] = 0ULL;

    for (int kt = 0; kt < 512; kt += 32) {
        __syncthreads();
        #pragma unroll
        for (int i = 0; i < 2; i++) {            // A tile: 64x32
            int s = tid + i * 256;
            int m = s >> 3, k4 = (s & 7) * 4;
            float4 v = *(const float4*)&g_htop[(size_t)(bm + m) * 512 + kt + k4];
            As[k4][m] = v.x; As[k4 + 1][m] = v.y; As[k4 + 2][m] = v.z; As[k4 + 3][m] = v.w;
        }
        #pragma unroll
        for (int i = 0; i < 4; i++) {            // B tile: 128x32
            int s = tid + i * 256;
            int n = s >> 3, k4 = (s & 7) * 4;
            float4 v = *(const float4*)&Wout[(size_t)(bn + n) * 512 + kt + k4];
            Bs[k4][n] = v.x; Bs[k4 + 1][n] = v.y; Bs[k4 + 2][n] = v.z; Bs[k4 + 3][n] = v.w;
        }
        __syncthreads();
        #pragma unroll
        for (int kk = 0; kk < 32; kk++) {
            float4 a4 = *(const float4*)&As[kk][ty * 4];
            u64 bv[4];
            #pragma unroll
            for (int jj = 0; jj < 4; jj++)       // n-pairs at stride 16 u64 -> conflict-free
                bv[jj] = *(const u64*)&Bs[kk][2 * tx + 32 * jj];
            u64 aa;
            aa = pk2(a4.x, a4.x);
            #pragma unroll
            for (int jj = 0; jj < 4; jj++) acc[0][jj] = ffma2(aa, bv[jj], acc[0][jj]);
            aa = pk2(a4.y, a4.y);
            #pragma unroll
            for (int jj = 0; jj < 4; jj++) acc[1][jj] = ffma2(aa, bv[jj], acc[1][jj]);
            aa = pk2(a4.z, a4.z);
            #pragma unroll
            for (int jj = 0; jj < 4; jj++) acc[2][jj] = ffma2(aa, bv[jj], acc[2][jj]);
            aa = pk2(a4.w, a4.w);
            #pragma unroll
            for (int jj = 0; jj < 4; jj++) acc[3][jj] = ffma2(aa, bv[jj], acc[3][jj]);
        }
    }

    #pragma unroll
    for (int i = 0; i < 4; i++) {
        int r = bm + ty * 4 + i;                 // r = t*32 + b
        if (r < 1632) {
            int tt = r >> 5, b = r & 31;
            size_t rowbase = (size_t)b * NT * NV + (size_t)tt * NV;
            #pragma unroll
            for (int jj = 0; jj < 4; jj++) {
                int n = bn + 2 * tx + 32 * jj;
                float lo, hi; upk2(acc[i][jj], lo, hi);
                float2 bo = *(const float2*)&bout[n];
                float2 res = make_float2(lo + bo.x, hi + bo.y);
                *(float2*)&out[rowbase + n] = res;
            }
        }
    }
}

// -------- final hidden state -> tail of d_out --------
__global__ void write_hfin(float* __restrict__ out) {
    int idx = blockIdx.x * blockDim.x + threadIdx.x;   // 65536
    out[(size_t)NB * NT * NV + idx] = (&g_h[1][0][0][0])[idx];
}

extern "C" void kernel_launch(void* const* d_in, const int* in_sizes, int n_in,
                              void* d_out, int out_size)
{
    (void)in_sizes; (void)n_in; (void)out_size;
    // metadata order: encoder_output, decoder_hidden, decoder_cell, target_tensor,
    //                 embedding, W_ih, W_hh, b_ih, b_hh, W_out, b_out
    const float* dh   = (const float*)d_in[1];
    const float* dc   = (const float*)d_in[2];
    const int*   tgt  = (const int*)  d_in[3];
    const float* emb  = (const float*)d_in[4];
    const float* Wih  = (const float*)d_in[5];
    const float* Whh  = (const float*)d_in[6];
    const float* bih  = (const float*)d_in[7];
    const float* bhh  = (const float*)d_in[8];
    const float* Wout = (const float*)d_in[9];
    const float* bout = (const float*)d_in[10];
    float* out = (float*)d_out;

    const int SMEM_LSTM = 16 * 1024 * 8 + 2 * 4 * 4 * 32 * 4;   // 135168 B
    cudaFuncSetAttribute(lstm_step, cudaFuncAttributeMaxDynamicSharedMemorySize, SMEM_LSTM);

    init_states<<<256, 256>>>(dh, dc);

    for (int t = 0; t < NT; t++)
        for (int l = 0; l < NL; l++)
            lstm_step<<<128, 256, SMEM_LSTM>>>(l, t, t & 1, emb, tgt, Wih, Whh, bih, bhh);

    proj_gemm<<<dim3(250, 26), 256>>>(Wout, bout, out);
    write_hfin<<<256, 256>>>(out);
}